// round 14
// baseline (speedup 1.0000x reference)
#include <cuda_runtime.h>
#include <math.h>

#define Bsz 8
#define Tt 12
#define Hh 256
#define Ww 256
#define EC 8
#define HC 16
#define HW (Hh*Ww)

// Scratch (device globals; no allocations allowed)
__device__ float g_e1 [Bsz*Tt*EC*HW];   // encoder conv1 output (96 frames x 8ch)
__device__ float g_enc[Bsz*Tt*EC*HW];   // encoder conv2 output
__device__ float g_h[2][Bsz*HC*HW];     // ping-pong hidden state
__device__ float g_c[2][Bsz*HC*HW];     // ping-pong cell state

__device__ __forceinline__ float sigmf(float x){ return 1.0f/(1.0f+expf(-x)); }

// ---- packed f32x2 helpers (sm_100+) ----
__device__ __forceinline__ void fma2(unsigned long long& acc,
                                     unsigned long long a,
                                     unsigned long long b){
    asm("fma.rn.f32x2 %0, %1, %2, %3;" : "=l"(acc) : "l"(a), "l"(b), "l"(acc));
}
__device__ __forceinline__ unsigned long long pack2(float v){
    unsigned long long r;
    asm("mov.b64 %0, {%1, %1};" : "=l"(r) : "f"(v));
    return r;
}
__device__ __forceinline__ void unpack2(unsigned long long v, float& lo, float& hi){
    asm("mov.b64 {%0, %1}, %2;" : "=f"(lo), "=f"(hi) : "l"(v));
}

__global__ void zero_state_kernel(){
    int idx = blockIdx.x*blockDim.x + threadIdx.x;
    if (idx < Bsz*HC*HW){ g_h[0][idx]=0.f; g_c[0][idx]=0.f; }
}

// ---------------- encoder conv1: 1 -> 8, 3x3, pad 1, relu ----------------
__global__ void enc1_kernel(const float* __restrict__ x,
                            const float* __restrict__ w,
                            const float* __restrict__ b){
    __shared__ float tile[10*34];
    __shared__ float ws[72];
    __shared__ float bs[8];
    int f   = blockIdx.z;                  // frame (b*T+t), 0..95
    int tid = threadIdx.y*32 + threadIdx.x;
    if (tid < 72) ws[tid] = w[tid];
    if (tid < 8)  bs[tid] = b[tid];
    const float* xin = x + (size_t)f*HW;
    int by0 = blockIdx.y*8, bx0 = blockIdx.x*32;
    for (int i = tid; i < 340; i += 256){
        int ly = i/34, lx = i%34;
        int gy = by0 + ly - 1, gx = bx0 + lx - 1;
        float v = 0.f;
        if (gy>=0 && gy<Hh && gx>=0 && gx<Ww) v = xin[gy*Ww+gx];
        tile[i] = v;
    }
    __syncthreads();
    float acc[8];
    #pragma unroll
    for (int o=0;o<8;o++) acc[o]=bs[o];
    int base = threadIdx.y*34 + threadIdx.x;
    #pragma unroll
    for (int k=0;k<9;k++){
        float v = tile[base + (k/3)*34 + (k%3)];
        #pragma unroll
        for (int o=0;o<8;o++) acc[o] = fmaf(ws[o*9+k], v, acc[o]);
    }
    int gy = by0 + threadIdx.y, gx = bx0 + threadIdx.x;
    float* outp = g_e1 + (size_t)f*EC*HW + gy*Ww + gx;
    #pragma unroll
    for (int o=0;o<8;o++) outp[(size_t)o*HW] = fmaxf(acc[o], 0.f);
}

// ---------------- encoder conv2: 8 -> 8, 3x3, pad 1, relu ----------------
// R9-style: 2 rows/thread, f32x2 over the 8 output channels (4 u64 acc/row).
__global__ __launch_bounds__(256, 4)
void enc2_kernel(const float* __restrict__ w,
                 const float* __restrict__ b){
    __shared__ float tile[8*18*34];                 // 4896 floats = 19.6KB
    __shared__ __align__(16) float ws[8*9*8];       // [cin][k][o]
    __shared__ float bs[8];
    int f   = blockIdx.z;
    int tx  = threadIdx.x, ty = threadIdx.y;
    int tid = ty*32 + tx;
    for (int i=tid; i<576; i+=256){
        int o = i & 7; int k = (i>>3)%9; int cin = i/72;
        ws[i] = w[(o*8+cin)*9 + k];
    }
    if (tid<8) bs[tid] = b[tid];
    const float* in = g_e1 + (size_t)f*EC*HW;
    int by0 = blockIdx.y*16, bx0 = blockIdx.x*32;
    for (int i=tid; i<8*612; i+=256){
        int c = i/612, rem = i%612;
        int ly = rem/34, lx = rem%34;
        int gy = by0+ly-1, gx = bx0+lx-1;
        tile[i] = (gy>=0 && gy<Hh && gx>=0 && gx<Ww) ? in[(size_t)c*HW + gy*Ww+gx] : 0.f;
    }
    __syncthreads();

    unsigned long long acc[4][2];
    #pragma unroll
    for (int j=0;j<4;j++){ acc[j][0]=0ULL; acc[j][1]=0ULL; }

    const float* tbase = tile + ty*2*34 + tx;
    const ulonglong2* wsv = (const ulonglong2*)ws;
    #pragma unroll 1
    for (int cin=0;cin<8;cin++){
        const float* tp = tbase + cin*612;
        #pragma unroll
        for (int k=0;k<9;k++){
            const int r = k/3, c = k%3;
            ulonglong2 wA = wsv[(cin*9+k)*2+0];   // pairs (o0,o1),(o2,o3)
            ulonglong2 wB = wsv[(cin*9+k)*2+1];   // pairs (o4,o5),(o6,o7)
            unsigned long long vv0 = pack2(tp[(r+0)*34 + c]);
            unsigned long long vv1 = pack2(tp[(r+1)*34 + c]);
            fma2(acc[0][0],vv0,wA.x); fma2(acc[1][0],vv0,wA.y);
            fma2(acc[2][0],vv0,wB.x); fma2(acc[3][0],vv0,wB.y);
            fma2(acc[0][1],vv1,wA.x); fma2(acc[1][1],vv1,wA.y);
            fma2(acc[2][1],vv1,wB.x); fma2(acc[3][1],vv1,wB.y);
        }
    }
    int gx = bx0 + tx;
    #pragma unroll
    for (int p=0;p<2;p++){
        int gy = by0 + ty*2 + p;
        float o8[8];
        #pragma unroll
        for (int j=0;j<4;j++) unpack2(acc[j][p], o8[2*j], o8[2*j+1]);
        float* outp = g_enc + (size_t)f*EC*HW + gy*Ww + gx;
        #pragma unroll
        for (int o=0;o<8;o++) outp[(size_t)o*HW] = fmaxf(o8[o]+bs[o], 0.f);
    }
}

// ---------------- ConvLSTM step: conv(cat(enc_t,h), 24 -> 64) + gates ----
// Grid (4, 128, B): hcg = blockIdx.x is FASTEST so the 4 hcg twins (which
// read identical enc+h tiles) get adjacent bids -> adjacent SMs, same wave
// -> 3 of 4 tile loads become L2 hits. Tile loads batched 4-wide for MLP.
// Mainloop/epilogue identical to R13 (the proven R9 optimum).
template<bool FIRST>
__global__ __launch_bounds__(256, 4)
void lstm_step_kernel(const float* __restrict__ cell_w,
                      const float* __restrict__ cell_b,
                      int t, int src){
    __shared__ float tile[12*18*34];                 // 7344 floats = 29.4KB
    __shared__ __align__(16) float ws[24*9*16];      // [cin][k][o_l], 13.8KB
    __shared__ float bs[16];
    int hcg = blockIdx.x;
    int b   = blockIdx.z;
    int bx0 = (blockIdx.y & 7)  * 32;
    int by0 = (blockIdx.y >> 3) * 16;
    int tx  = threadIdx.x, ty = threadIdx.y;
    int tid = ty*32 + tx;

    const int WLIM = FIRST ? 8*144 : 3456;
    for (int i = tid; i < WLIM; i += 256){
        int o_l = i & 15;
        int k   = (i >> 4) % 9;
        int cin = i / 144;
        int row = (o_l>>2)*16 + hcg*4 + (o_l&3);     // gate*16 + hc
        ws[i] = cell_w[(row*24 + cin)*9 + k];
    }
    if (tid < 16) bs[tid] = cell_b[(tid>>2)*16 + hcg*4 + (tid&3)];

    const float* enc_t = g_enc + (size_t)((b*Tt + t)*EC)*HW;
    const float* h_src = g_h[src] + (size_t)b*HC*HW;

    // acc[j][p]: lane pair = output channels (2j, 2j+1), p = pixel row 0..1
    unsigned long long acc[8][2];
    #pragma unroll
    for (int j=0;j<8;j++)
        #pragma unroll
        for (int p=0;p<2;p++) acc[j][p]=0ULL;

    const int NPH = FIRST ? 1 : 2;
    const int CPP = FIRST ? 8 : 12;
    #pragma unroll
    for (int phase=0; phase<NPH; phase++){
        const int TOT = CPP*612;
        __syncthreads();            // wait until all reads of prior tile done
        // 4-wide batched load: issue 4 guarded LDGs before the 4 STS (MLP>=4)
        #pragma unroll 1
        for (int i0 = tid; i0 < TOT; i0 += 1024){
            float v[4];
            #pragma unroll
            for (int j=0;j<4;j++){
                int i = i0 + j*256;
                v[j] = 0.f;
                if (i < TOT){
                    int cl = i / 612, rem = i % 612;
                    int ly = rem / 34, lx = rem % 34;
                    int c  = cl + phase*12;
                    int gy = by0 + ly - 1, gx = bx0 + lx - 1;
                    if (gy>=0 && gy<Hh && gx>=0 && gx<Ww){
                        v[j] = (c < EC) ? enc_t[(size_t)c*HW + gy*Ww + gx]
                                        : h_src[(size_t)(c-EC)*HW + gy*Ww + gx];
                    }
                }
            }
            #pragma unroll
            for (int j=0;j<4;j++){
                int i = i0 + j*256;
                if (i < TOT) tile[i] = v[j];
            }
        }
        __syncthreads();

        const float* tbase = tile + ty*2*34 + tx;
        #pragma unroll 1
        for (int cl=0; cl<CPP; cl++){
            const float*      tp = tbase + cl*612;
            const ulonglong2* wp = (const ulonglong2*)(ws + (size_t)(phase*12 + cl)*144);
            #pragma unroll
            for (int k=0;k<9;k++){
                const int r = k/3, c = k%3;
                ulonglong2 wA = wp[k*4+0];   // pairs (o0,o1),(o2,o3)
                ulonglong2 wB = wp[k*4+1];   // pairs (o4,o5),(o6,o7)
                ulonglong2 wC = wp[k*4+2];   // pairs (o8,o9),(o10,o11)
                ulonglong2 wD = wp[k*4+3];   // pairs (o12,o13),(o14,o15)
                unsigned long long vv0 = pack2(tp[(r+0)*34 + c]);
                unsigned long long vv1 = pack2(tp[(r+1)*34 + c]);
                #define STEP8(P, V) \
                    fma2(acc[0][P], V, wA.x); fma2(acc[1][P], V, wA.y); \
                    fma2(acc[2][P], V, wB.x); fma2(acc[3][P], V, wB.y); \
                    fma2(acc[4][P], V, wC.x); fma2(acc[5][P], V, wC.y); \
                    fma2(acc[6][P], V, wD.x); fma2(acc[7][P], V, wD.y);
                STEP8(0, vv0)
                STEP8(1, vv1)
                #undef STEP8
            }
        }
    }

    int gx  = bx0 + tx;
    int dst = src ^ 1;
    const float* c_src_p = g_c[src] + (size_t)b*HC*HW;
    float*       c_dst_p = g_c[dst] + (size_t)b*HC*HW;
    float*       h_dst_p = g_h[dst] + (size_t)b*HC*HW;
    #pragma unroll
    for (int p=0;p<2;p++){
        int gy = by0 + ty*2 + p;
        int pi = gy*Ww + gx;
        float g16[16];
        #pragma unroll
        for (int j=0;j<8;j++) unpack2(acc[j][p], g16[2*j], g16[2*j+1]);
        #pragma unroll
        for (int l=0;l<4;l++){
            int hc = hcg*4 + l;
            float ig = sigmf(g16[l]    + bs[l]);
            float og = sigmf(g16[8+l]  + bs[8+l]);
            float gg = tanhf(g16[12+l] + bs[12+l]);
            float cn;
            if (FIRST){
                cn = ig*gg;                       // f*c0 = 0 exactly
            } else {
                float fg = sigmf(g16[4+l]  + bs[4+l]);
                float cp = c_src_p[(size_t)hc*HW + pi];
                cn = fg*cp + ig*gg;
            }
            c_dst_p[(size_t)hc*HW + pi] = cn;
            h_dst_p[(size_t)hc*HW + pi] = og * tanhf(cn);
        }
    }
}

// ---------------- fused epilogue: mean/wp/gate/head/sigmoid --------------
__global__ void fuse_kernel(const float* __restrict__ sat, const int* __restrict__ months,
                            const float* __restrict__ wp_w, const float* __restrict__ wp_b,
                            const float* __restrict__ head_w, const float* __restrict__ head_b,
                            const float* __restrict__ sg_w1, const float* __restrict__ sg_b1,
                            const float* __restrict__ sg_w2, const float* __restrict__ sg_b2,
                            float* __restrict__ out){
    int idx = blockIdx.x*blockDim.x + threadIdx.x;
    if (idx >= Bsz*HW) return;
    int b = idx / HW, p = idx % HW;

    // scalar sat gate (1->8->1 MLP) + month prior
    float s = sat[b];
    float pre = sg_b2[0];
    #pragma unroll
    for (int j=0;j<8;j++){
        float hid = fmaxf(fmaf(sg_w1[j], s, sg_b1[j]), 0.f);
        pre = fmaf(sg_w2[j], hid, pre);
    }
    int m = months[b];
    float prior = (m>=3 && m<=6) ? 0.6f : 0.3f;
    float alpha = prior * sigmf(pre);

    // temporal mean of encoder features
    float feat[8];
    #pragma unroll
    for (int c=0;c<8;c++){
        float a = 0.f;
        #pragma unroll
        for (int t=0;t<Tt;t++) a += g_enc[(size_t)((b*Tt+t)*EC+c)*HW + p];
        feat[c] = a * (1.0f/12.0f);
    }

    // wp 1x1 conv + fuse + head 1x1 conv + sigmoid
    float res = head_b[0];
    #pragma unroll
    for (int hc=0; hc<16; hc++){
        float haux = wp_b[hc];
        #pragma unroll
        for (int c=0;c<8;c++) haux = fmaf(wp_w[hc*8+c], feat[c], haux);
        float hm = g_h[0][(size_t)(b*HC+hc)*HW + p];   // after 12 steps h lives in buf 0
        res = fmaf(head_w[hc], hm + alpha*haux, res);
    }
    out[idx] = sigmf(res);
}

extern "C" void kernel_launch(void* const* d_in, const int* in_sizes, int n_in,
                              void* d_out, int out_size){
    const float* x       = (const float*)d_in[0];
    const float* sat     = (const float*)d_in[1];
    const int*   months  = (const int*)  d_in[2];
    const float* enc_w1  = (const float*)d_in[3];
    const float* enc_b1  = (const float*)d_in[4];
    const float* enc_w2  = (const float*)d_in[5];
    const float* enc_b2  = (const float*)d_in[6];
    const float* cell_w  = (const float*)d_in[7];
    const float* cell_b  = (const float*)d_in[8];
    const float* wp_w    = (const float*)d_in[9];
    const float* wp_b    = (const float*)d_in[10];
    const float* head_w  = (const float*)d_in[11];
    const float* head_b  = (const float*)d_in[12];
    const float* sg_w1   = (const float*)d_in[13];
    const float* sg_b1   = (const float*)d_in[14];
    const float* sg_w2   = (const float*)d_in[15];
    const float* sg_b2   = (const float*)d_in[16];
    float* out = (float*)d_out;

    dim3 blk256(32, 8);
    zero_state_kernel<<<(Bsz*HC*HW + 255)/256, 256>>>();
    enc1_kernel<<<dim3(8, 32, Bsz*Tt), blk256>>>(x, enc_w1, enc_b1);
    enc2_kernel<<<dim3(8, 16, Bsz*Tt), blk256>>>(enc_w2, enc_b2);
    // grid: x = hcg (fastest -> twins adjacent), y = tile (8x16), z = batch
    dim3 lstm_grid(4, 128, Bsz);
    // t=0: h=c=0 -> specialized kernel (8 input channels, no c read)
    lstm_step_kernel<true><<<lstm_grid, blk256>>>(cell_w, cell_b, 0, 0);
    for (int t=1; t<Tt; t++){
        // src parity: t even reads buf0, writes buf1; final h lands in buf0
        lstm_step_kernel<false><<<lstm_grid, blk256>>>(cell_w, cell_b, t, t & 1);
    }
    fuse_kernel<<<(Bsz*HW + 255)/256, 256>>>(sat, months, wp_w, wp_b,
                                             head_w, head_b, sg_w1, sg_b1,
                                             sg_w2, sg_b2, out);
}

// round 15
// speedup vs baseline: 1.0971x; 1.0971x over previous
#include <cuda_runtime.h>
#include <math.h>

#define Bsz 8
#define Tt 12
#define Hh 256
#define Ww 256
#define EC 8
#define HC 16
#define HW (Hh*Ww)

// Scratch (device globals; no allocations allowed)
__device__ float g_enc[Bsz*Tt*EC*HW];   // encoder output (fused enc1+enc2)
__device__ float g_h[2][Bsz*HC*HW];     // ping-pong hidden state
__device__ float g_c[2][Bsz*HC*HW];     // ping-pong cell state
__device__ float g_wperm[4*24*9*16];    // per-hcg permuted cell weights

__device__ __forceinline__ float sigmf_fast(float x){
    return __fdividef(1.0f, 1.0f + __expf(-x));
}
__device__ __forceinline__ float tanhf_fast(float x){
    return __fdividef(2.0f, 1.0f + __expf(-2.0f*x)) - 1.0f;
}

// ---- packed f32x2 helpers (sm_100+) ----
__device__ __forceinline__ void fma2(unsigned long long& acc,
                                     unsigned long long a,
                                     unsigned long long b){
    asm("fma.rn.f32x2 %0, %1, %2, %3;" : "=l"(acc) : "l"(a), "l"(b), "l"(acc));
}
__device__ __forceinline__ unsigned long long pack2(float v){
    unsigned long long r;
    asm("mov.b64 %0, {%1, %1};" : "=l"(r) : "f"(v));
    return r;
}
__device__ __forceinline__ void unpack2(unsigned long long v, float& lo, float& hi){
    asm("mov.b64 {%0, %1}, %2;" : "=f"(lo), "=f"(hi) : "l"(v));
}

// Permute cell_w [64][24][9] -> g_wperm [hcg][cin*9*16 + k*16 + o_l]
// o_l = gate*4 + l ; row = gate*16 + hcg*4 + l. Makes lstm ws loads coalesced.
__global__ void permute_w_kernel(const float* __restrict__ cell_w){
    int i = blockIdx.x*blockDim.x + threadIdx.x;
    if (i >= 4*3456) return;
    int hcg = i / 3456;
    int r   = i % 3456;
    int o_l = r & 15;
    int k   = (r >> 4) % 9;
    int cin = r / 144;
    int row = (o_l>>2)*16 + hcg*4 + (o_l&3);
    g_wperm[i] = cell_w[(row*24 + cin)*9 + k];
}

// ------------- fused encoder: conv1(1->8)+relu then conv2(8->8)+relu ------
// e1 computed into smem with halo; g_e1 gmem roundtrip eliminated.
__global__ __launch_bounds__(256)
void enc12_kernel(const float* __restrict__ x,
                  const float* __restrict__ w1, const float* __restrict__ b1,
                  const float* __restrict__ w2, const float* __restrict__ b2){
    __shared__ float xs[20*36];                     // x region (halo 2)
    __shared__ float e1s[8*18*34];                  // e1 region (halo 1), [c][612]
    __shared__ float ws1[72];
    __shared__ float bs1[8];
    __shared__ __align__(16) float ws2[8*9*8];      // [cin][k][o]
    __shared__ float bs2[8];
    int f   = blockIdx.z;                           // frame b*T+t
    int tx  = threadIdx.x, ty = threadIdx.y;
    int tid = ty*32 + tx;
    int by0 = blockIdx.y*16, bx0 = blockIdx.x*32;

    if (tid < 72) ws1[tid] = w1[tid];
    if (tid >= 96 && tid < 104) bs1[tid-96] = b1[tid-96];
    for (int i=tid; i<576; i+=256){
        int o = i & 7; int k = (i>>3)%9; int cin = i/72;
        ws2[i] = w2[(o*8+cin)*9 + k];
    }
    if (tid >= 128 && tid < 136) bs2[tid-128] = b2[tid-128];

    const float* xin = x + (size_t)f*HW;
    for (int i = tid; i < 720; i += 256){
        int ly = i/36, lx = i%36;
        int gy = by0 + ly - 2, gx = bx0 + lx - 2;
        float v = 0.f;
        if (gy>=0 && gy<Hh && gx>=0 && gx<Ww) v = xin[gy*Ww+gx];
        xs[i] = v;
    }
    __syncthreads();

    // e1 over 18x34 region: e1 local (ly,lx) reads xs[ly+r][lx+c]
    for (int i = tid; i < 612; i += 256){
        int ly = i/34, lx = i%34;
        float acc[8];
        #pragma unroll
        for (int o=0;o<8;o++) acc[o]=bs1[o];
        #pragma unroll
        for (int k=0;k<9;k++){
            float v = xs[(ly + k/3)*36 + lx + (k%3)];
            #pragma unroll
            for (int o=0;o<8;o++) acc[o] = fmaf(ws1[o*9+k], v, acc[o]);
        }
        #pragma unroll
        for (int o=0;o<8;o++) e1s[o*612 + i] = fmaxf(acc[o], 0.f);
    }
    __syncthreads();

    // conv2: 2 rows/thread, f32x2 over 8 output channels
    unsigned long long acc[4][2];
    #pragma unroll
    for (int j=0;j<4;j++){ acc[j][0]=0ULL; acc[j][1]=0ULL; }
    const float* tbase = e1s + ty*2*34 + tx;
    const ulonglong2* wsv = (const ulonglong2*)ws2;
    #pragma unroll 1
    for (int cin=0;cin<8;cin++){
        const float* tp = tbase + cin*612;
        #pragma unroll
        for (int k=0;k<9;k++){
            const int r = k/3, c = k%3;
            ulonglong2 wA = wsv[(cin*9+k)*2+0];
            ulonglong2 wB = wsv[(cin*9+k)*2+1];
            unsigned long long vv0 = pack2(tp[(r+0)*34 + c]);
            unsigned long long vv1 = pack2(tp[(r+1)*34 + c]);
            fma2(acc[0][0],vv0,wA.x); fma2(acc[1][0],vv0,wA.y);
            fma2(acc[2][0],vv0,wB.x); fma2(acc[3][0],vv0,wB.y);
            fma2(acc[0][1],vv1,wA.x); fma2(acc[1][1],vv1,wA.y);
            fma2(acc[2][1],vv1,wB.x); fma2(acc[3][1],vv1,wB.y);
        }
    }
    int gx = bx0 + tx;
    #pragma unroll
    for (int p=0;p<2;p++){
        int gy = by0 + ty*2 + p;
        float o8[8];
        #pragma unroll
        for (int j=0;j<4;j++) unpack2(acc[j][p], o8[2*j], o8[2*j+1]);
        float* outp = g_enc + (size_t)f*EC*HW + gy*Ww + gx;
        #pragma unroll
        for (int o=0;o<8;o++) outp[(size_t)o*HW] = fmaxf(o8[o]+bs2[o], 0.f);
    }
}

// ---------------- ConvLSTM step: conv(cat(enc_t,h), 24 -> 64) + gates ----
// R14 structure: grid (4,128,B) twins adjacent; MLP-4 tile loads; weights now
// loaded COALESCED (float4) from pre-permuted g_wperm; fast-math gate epilogue.
template<bool FIRST>
__global__ __launch_bounds__(256, 4)
void lstm_step_kernel(const float* __restrict__ cell_b,
                      int t, int src){
    __shared__ float tile[12*18*34];                 // 7344 floats = 29.4KB
    __shared__ __align__(16) float ws[24*9*16];      // [cin][k][o_l], 13.8KB
    __shared__ float bs[16];
    int hcg = blockIdx.x;
    int b   = blockIdx.z;
    int bx0 = (blockIdx.y & 7)  * 32;
    int by0 = (blockIdx.y >> 3) * 16;
    int tx  = threadIdx.x, ty = threadIdx.y;
    int tid = ty*32 + tx;

    {   // coalesced weight prologue
        const float4* src4 = (const float4*)(g_wperm + hcg*3456);
        float4*       dst4 = (float4*)ws;
        const int N4 = (FIRST ? 1152 : 3456) / 4;
        for (int i = tid; i < N4; i += 256) dst4[i] = src4[i];
    }
    if (tid < 16) bs[tid] = cell_b[(tid>>2)*16 + hcg*4 + (tid&3)];

    const float* enc_t = g_enc + (size_t)((b*Tt + t)*EC)*HW;
    const float* h_src = g_h[src] + (size_t)b*HC*HW;

    unsigned long long acc[8][2];
    #pragma unroll
    for (int j=0;j<8;j++)
        #pragma unroll
        for (int p=0;p<2;p++) acc[j][p]=0ULL;

    const int NPH = FIRST ? 1 : 2;
    const int CPP = FIRST ? 8 : 12;
    #pragma unroll
    for (int phase=0; phase<NPH; phase++){
        const int TOT = CPP*612;
        __syncthreads();
        #pragma unroll 1
        for (int i0 = tid; i0 < TOT; i0 += 1024){
            float v[4];
            #pragma unroll
            for (int j=0;j<4;j++){
                int i = i0 + j*256;
                v[j] = 0.f;
                if (i < TOT){
                    int cl = i / 612, rem = i % 612;
                    int ly = rem / 34, lx = rem % 34;
                    int c  = cl + phase*12;
                    int gy = by0 + ly - 1, gx = bx0 + lx - 1;
                    if (gy>=0 && gy<Hh && gx>=0 && gx<Ww){
                        v[j] = (c < EC) ? enc_t[(size_t)c*HW + gy*Ww + gx]
                                        : h_src[(size_t)(c-EC)*HW + gy*Ww + gx];
                    }
                }
            }
            #pragma unroll
            for (int j=0;j<4;j++){
                int i = i0 + j*256;
                if (i < TOT) tile[i] = v[j];
            }
        }
        __syncthreads();

        const float* tbase = tile + ty*2*34 + tx;
        #pragma unroll 1
        for (int cl=0; cl<CPP; cl++){
            const float*      tp = tbase + cl*612;
            const ulonglong2* wp = (const ulonglong2*)(ws + (size_t)(phase*12 + cl)*144);
            #pragma unroll
            for (int k=0;k<9;k++){
                const int r = k/3, c = k%3;
                ulonglong2 wA = wp[k*4+0];
                ulonglong2 wB = wp[k*4+1];
                ulonglong2 wC = wp[k*4+2];
                ulonglong2 wD = wp[k*4+3];
                unsigned long long vv0 = pack2(tp[(r+0)*34 + c]);
                unsigned long long vv1 = pack2(tp[(r+1)*34 + c]);
                #define STEP8(P, V) \
                    fma2(acc[0][P], V, wA.x); fma2(acc[1][P], V, wA.y); \
                    fma2(acc[2][P], V, wB.x); fma2(acc[3][P], V, wB.y); \
                    fma2(acc[4][P], V, wC.x); fma2(acc[5][P], V, wC.y); \
                    fma2(acc[6][P], V, wD.x); fma2(acc[7][P], V, wD.y);
                STEP8(0, vv0)
                STEP8(1, vv1)
                #undef STEP8
            }
        }
    }

    int gx  = bx0 + tx;
    int dst = src ^ 1;
    const float* c_src_p = g_c[src] + (size_t)b*HC*HW;
    float*       c_dst_p = g_c[dst] + (size_t)b*HC*HW;
    float*       h_dst_p = g_h[dst] + (size_t)b*HC*HW;
    #pragma unroll
    for (int p=0;p<2;p++){
        int gy = by0 + ty*2 + p;
        int pi = gy*Ww + gx;
        float g16[16];
        #pragma unroll
        for (int j=0;j<8;j++) unpack2(acc[j][p], g16[2*j], g16[2*j+1]);
        #pragma unroll
        for (int l=0;l<4;l++){
            int hc = hcg*4 + l;
            float ig = sigmf_fast(g16[l]    + bs[l]);
            float og = sigmf_fast(g16[8+l]  + bs[8+l]);
            float gg = tanhf_fast(g16[12+l] + bs[12+l]);
            float cn;
            if (FIRST){
                cn = ig*gg;                       // f*c0 = 0 exactly
            } else {
                float fg = sigmf_fast(g16[4+l]  + bs[4+l]);
                float cp = c_src_p[(size_t)hc*HW + pi];
                cn = fg*cp + ig*gg;
            }
            c_dst_p[(size_t)hc*HW + pi] = cn;
            h_dst_p[(size_t)hc*HW + pi] = og * tanhf_fast(cn);
        }
    }
}

// ---------------- fused epilogue: mean/wp/gate/head/sigmoid --------------
__global__ void fuse_kernel(const float* __restrict__ sat, const int* __restrict__ months,
                            const float* __restrict__ wp_w, const float* __restrict__ wp_b,
                            const float* __restrict__ head_w, const float* __restrict__ head_b,
                            const float* __restrict__ sg_w1, const float* __restrict__ sg_b1,
                            const float* __restrict__ sg_w2, const float* __restrict__ sg_b2,
                            float* __restrict__ out){
    int idx = blockIdx.x*blockDim.x + threadIdx.x;
    if (idx >= Bsz*HW) return;
    int b = idx / HW, p = idx % HW;

    float s = sat[b];
    float pre = sg_b2[0];
    #pragma unroll
    for (int j=0;j<8;j++){
        float hid = fmaxf(fmaf(sg_w1[j], s, sg_b1[j]), 0.f);
        pre = fmaf(sg_w2[j], hid, pre);
    }
    int m = months[b];
    float prior = (m>=3 && m<=6) ? 0.6f : 0.3f;
    float alpha = prior * sigmf_fast(pre);

    float feat[8];
    #pragma unroll
    for (int c=0;c<8;c++){
        float a = 0.f;
        #pragma unroll
        for (int t=0;t<Tt;t++) a += g_enc[(size_t)((b*Tt+t)*EC+c)*HW + p];
        feat[c] = a * (1.0f/12.0f);
    }

    float res = head_b[0];
    #pragma unroll
    for (int hc=0; hc<16; hc++){
        float haux = wp_b[hc];
        #pragma unroll
        for (int c=0;c<8;c++) haux = fmaf(wp_w[hc*8+c], feat[c], haux);
        float hm = g_h[0][(size_t)(b*HC+hc)*HW + p];   // after 12 steps h lives in buf 0
        res = fmaf(head_w[hc], hm + alpha*haux, res);
    }
    out[idx] = sigmf_fast(res);
}

extern "C" void kernel_launch(void* const* d_in, const int* in_sizes, int n_in,
                              void* d_out, int out_size){
    const float* x       = (const float*)d_in[0];
    const float* sat     = (const float*)d_in[1];
    const int*   months  = (const int*)  d_in[2];
    const float* enc_w1  = (const float*)d_in[3];
    const float* enc_b1  = (const float*)d_in[4];
    const float* enc_w2  = (const float*)d_in[5];
    const float* enc_b2  = (const float*)d_in[6];
    const float* cell_w  = (const float*)d_in[7];
    const float* cell_b  = (const float*)d_in[8];
    const float* wp_w    = (const float*)d_in[9];
    const float* wp_b    = (const float*)d_in[10];
    const float* head_w  = (const float*)d_in[11];
    const float* head_b  = (const float*)d_in[12];
    const float* sg_w1   = (const float*)d_in[13];
    const float* sg_b1   = (const float*)d_in[14];
    const float* sg_w2   = (const float*)d_in[15];
    const float* sg_b2   = (const float*)d_in[16];
    float* out = (float*)d_out;

    dim3 blk256(32, 8);
    permute_w_kernel<<<(4*3456 + 255)/256, 256>>>(cell_w);
    enc12_kernel<<<dim3(8, 16, Bsz*Tt), blk256>>>(x, enc_w1, enc_b1, enc_w2, enc_b2);
    // grid: x = hcg (twins adjacent), y = tile (8x16), z = batch
    dim3 lstm_grid(4, 128, Bsz);
    lstm_step_kernel<true><<<lstm_grid, blk256>>>(cell_b, 0, 0);
    for (int t=1; t<Tt; t++){
        lstm_step_kernel<false><<<lstm_grid, blk256>>>(cell_b, t, t & 1);
    }
    fuse_kernel<<<(Bsz*HW + 255)/256, 256>>>(sat, months, wp_w, wp_b,
                                             head_w, head_b, sg_w1, sg_b1,
                                             sg_w2, sg_b2, out);
}

// round 17
// speedup vs baseline: 1.1865x; 1.0815x over previous
#include <cuda_runtime.h>
#include <math.h>

#define Bsz 8
#define Tt 12
#define Hh 256
#define Ww 256
#define EC 8
#define HC 16
#define HW (Hh*Ww)

// Scratch (device globals; no allocations allowed)
__device__ float g_enc[Bsz*Tt*EC*HW];   // encoder output (fused enc1+enc2)
__device__ float g_h[2][Bsz*HC*HW];     // ping-pong hidden state
__device__ float g_c[2][Bsz*HC*HW];     // ping-pong cell state
__device__ float g_wperm[4*24*9*16];    // per-hcg permuted cell weights

__device__ __forceinline__ float sigmf_fast(float x){
    return __fdividef(1.0f, 1.0f + __expf(-x));
}
__device__ __forceinline__ float tanhf_fast(float x){
    return __fdividef(2.0f, 1.0f + __expf(-2.0f*x)) - 1.0f;
}

// ---- packed f32x2 helpers (sm_100+) ----
__device__ __forceinline__ void fma2(unsigned long long& acc,
                                     unsigned long long a,
                                     unsigned long long b){
    asm("fma.rn.f32x2 %0, %1, %2, %3;" : "=l"(acc) : "l"(a), "l"(b), "l"(acc));
}
__device__ __forceinline__ unsigned long long pack2(float v){
    unsigned long long r;
    asm("mov.b64 %0, {%1, %1};" : "=l"(r) : "f"(v));
    return r;
}
__device__ __forceinline__ void unpack2(unsigned long long v, float& lo, float& hi){
    asm("mov.b64 {%0, %1}, %2;" : "=f"(lo), "=f"(hi) : "l"(v));
}

// Permute cell_w [64][24][9] -> g_wperm [hcg][cin*9*16 + k*16 + o_l]
__global__ void permute_w_kernel(const float* __restrict__ cell_w){
    int i = blockIdx.x*blockDim.x + threadIdx.x;
    if (i >= 4*3456) return;
    int hcg = i / 3456;
    int r   = i % 3456;
    int o_l = r & 15;
    int k   = (r >> 4) % 9;
    int cin = r / 144;
    int row = (o_l>>2)*16 + hcg*4 + (o_l&3);
    g_wperm[i] = cell_w[(row*24 + cin)*9 + k];
}

// ------------- fused encoder: conv1(1->8)+relu then conv2(8->8)+relu ------
__global__ __launch_bounds__(256)
void enc12_kernel(const float* __restrict__ x,
                  const float* __restrict__ w1, const float* __restrict__ b1,
                  const float* __restrict__ w2, const float* __restrict__ b2){
    __shared__ float xs[20*36];                     // x region (halo 2)
    __shared__ float e1s[8*18*34];                  // e1 region (halo 1), [c][612]
    __shared__ float ws1[72];
    __shared__ float bs1[8];
    __shared__ __align__(16) float ws2[8*9*8];      // [cin][k][o]
    __shared__ float bs2[8];
    int f   = blockIdx.z;                           // frame b*T+t
    int tx  = threadIdx.x, ty = threadIdx.y;
    int tid = ty*32 + tx;
    int by0 = blockIdx.y*16, bx0 = blockIdx.x*32;

    if (tid < 72) ws1[tid] = w1[tid];
    if (tid >= 96 && tid < 104) bs1[tid-96] = b1[tid-96];
    for (int i=tid; i<576; i+=256){
        int o = i & 7; int k = (i>>3)%9; int cin = i/72;
        ws2[i] = w2[(o*8+cin)*9 + k];
    }
    if (tid >= 128 && tid < 136) bs2[tid-128] = b2[tid-128];

    const float* xin = x + (size_t)f*HW;
    for (int i = tid; i < 720; i += 256){
        int ly = i/36, lx = i%36;
        int gy = by0 + ly - 2, gx = bx0 + lx - 2;
        float v = 0.f;
        if (gy>=0 && gy<Hh && gx>=0 && gx<Ww) v = xin[gy*Ww+gx];
        xs[i] = v;
    }
    __syncthreads();

    for (int i = tid; i < 612; i += 256){
        int ly = i/34, lx = i%34;
        float acc[8];
        #pragma unroll
        for (int o=0;o<8;o++) acc[o]=bs1[o];
        #pragma unroll
        for (int k=0;k<9;k++){
            float v = xs[(ly + k/3)*36 + lx + (k%3)];
            #pragma unroll
            for (int o=0;o<8;o++) acc[o] = fmaf(ws1[o*9+k], v, acc[o]);
        }
        #pragma unroll
        for (int o=0;o<8;o++) e1s[o*612 + i] = fmaxf(acc[o], 0.f);
    }
    __syncthreads();

    unsigned long long acc[4][2];
    #pragma unroll
    for (int j=0;j<4;j++){ acc[j][0]=0ULL; acc[j][1]=0ULL; }
    const float* tbase = e1s + ty*2*34 + tx;
    const ulonglong2* wsv = (const ulonglong2*)ws2;
    #pragma unroll 1
    for (int cin=0;cin<8;cin++){
        const float* tp = tbase + cin*612;
        #pragma unroll
        for (int k=0;k<9;k++){
            const int r = k/3, c = k%3;
            ulonglong2 wA = wsv[(cin*9+k)*2+0];
            ulonglong2 wB = wsv[(cin*9+k)*2+1];
            unsigned long long vv0 = pack2(tp[(r+0)*34 + c]);
            unsigned long long vv1 = pack2(tp[(r+1)*34 + c]);
            fma2(acc[0][0],vv0,wA.x); fma2(acc[1][0],vv0,wA.y);
            fma2(acc[2][0],vv0,wB.x); fma2(acc[3][0],vv0,wB.y);
            fma2(acc[0][1],vv1,wA.x); fma2(acc[1][1],vv1,wA.y);
            fma2(acc[2][1],vv1,wB.x); fma2(acc[3][1],vv1,wB.y);
        }
    }
    int gx = bx0 + tx;
    #pragma unroll
    for (int p=0;p<2;p++){
        int gy = by0 + ty*2 + p;
        float o8[8];
        #pragma unroll
        for (int j=0;j<4;j++) unpack2(acc[j][p], o8[2*j], o8[2*j+1]);
        float* outp = g_enc + (size_t)f*EC*HW + gy*Ww + gx;
        #pragma unroll
        for (int o=0;o<8;o++) outp[(size_t)o*HW] = fmaxf(o8[o]+bs2[o], 0.f);
    }
}

// ---------------- ConvLSTM step: conv(cat(enc_t,h), 24 -> 64) + gates ----
// R15 structure; tile-load indexing hoisted: each thread's 3 plane positions
// (tid, tid+256, tid+512) -> (valid, gmem offset) computed ONCE, then the
// per-channel loop is pointer-select + 3 predicated LDG + 3 STS. Mainloop
// and epilogue identical to R15.
template<bool FIRST>
__global__ __launch_bounds__(256, 4)
void lstm_step_kernel(const float* __restrict__ cell_b,
                      int t, int src){
    __shared__ float tile[12*18*34];                 // 7344 floats = 29.4KB
    __shared__ __align__(16) float ws[24*9*16];      // [cin][k][o_l], 13.8KB
    __shared__ float bs[16];
    int hcg = blockIdx.x;
    int b   = blockIdx.z;
    int bx0 = (blockIdx.y & 7)  * 32;
    int by0 = (blockIdx.y >> 3) * 16;
    int tx  = threadIdx.x, ty = threadIdx.y;
    int tid = ty*32 + tx;

    {   // coalesced weight prologue
        const float4* src4 = (const float4*)(g_wperm + hcg*3456);
        float4*       dst4 = (float4*)ws;
        const int N4 = (FIRST ? 1152 : 3456) / 4;
        for (int i = tid; i < N4; i += 256) dst4[i] = src4[i];
    }
    if (tid < 16) bs[tid] = cell_b[(tid>>2)*16 + hcg*4 + (tid&3)];

    const float* enc_t = g_enc + (size_t)((b*Tt + t)*EC)*HW;
    const float* h_src = g_h[src] + (size_t)b*HC*HW;

    // Hoisted load indexing: 3 strided positions in the 612-element plane.
    const int p0 = tid, p1 = tid + 256, p2 = tid + 512;
    const bool has2 = (p2 < 612);
    int ly0 = p0/34, lx0 = p0%34;
    int ly1 = p1/34, lx1 = p1%34;
    int ly2 = p2/34, lx2 = p2%34;
    int gy0 = by0+ly0-1, gx0 = bx0+lx0-1;
    int gy1 = by0+ly1-1, gx1 = bx0+lx1-1;
    int gy2 = by0+ly2-1, gx2 = bx0+lx2-1;
    const bool v0ok = (gy0>=0 && gy0<Hh && gx0>=0 && gx0<Ww);
    const bool v1ok = (gy1>=0 && gy1<Hh && gx1>=0 && gx1<Ww);
    const bool v2ok = has2 && (gy2>=0 && gy2<Hh && gx2>=0 && gx2<Ww);
    const int off0 = gy0*Ww + gx0;
    const int off1 = gy1*Ww + gx1;
    const int off2 = gy2*Ww + gx2;

    unsigned long long acc[8][2];
    #pragma unroll
    for (int j=0;j<8;j++)
        #pragma unroll
        for (int p=0;p<2;p++) acc[j][p]=0ULL;

    const int NPH = FIRST ? 1 : 2;
    const int CPP = FIRST ? 8 : 12;
    #pragma unroll
    for (int phase=0; phase<NPH; phase++){
        __syncthreads();
        #pragma unroll 2
        for (int cl=0; cl<CPP; cl++){
            int c = cl + phase*12;
            const float* base = (c < EC) ? enc_t + (size_t)c*HW
                                         : h_src + (size_t)(c-EC)*HW;
            float v0 = v0ok ? __ldg(base + off0) : 0.f;
            float v1 = v1ok ? __ldg(base + off1) : 0.f;
            float v2 = v2ok ? __ldg(base + off2) : 0.f;
            float* td = tile + cl*612;
            td[p0] = v0;
            td[p1] = v1;
            if (has2) td[p2] = v2;
        }
        __syncthreads();

        const float* tbase = tile + ty*2*34 + tx;
        #pragma unroll 1
        for (int cl=0; cl<CPP; cl++){
            const float*      tp = tbase + cl*612;
            const ulonglong2* wp = (const ulonglong2*)(ws + (size_t)(phase*12 + cl)*144);
            #pragma unroll
            for (int k=0;k<9;k++){
                const int r = k/3, c = k%3;
                ulonglong2 wA = wp[k*4+0];
                ulonglong2 wB = wp[k*4+1];
                ulonglong2 wC = wp[k*4+2];
                ulonglong2 wD = wp[k*4+3];
                unsigned long long vv0 = pack2(tp[(r+0)*34 + c]);
                unsigned long long vv1 = pack2(tp[(r+1)*34 + c]);
                #define STEP8(P, V) \
                    fma2(acc[0][P], V, wA.x); fma2(acc[1][P], V, wA.y); \
                    fma2(acc[2][P], V, wB.x); fma2(acc[3][P], V, wB.y); \
                    fma2(acc[4][P], V, wC.x); fma2(acc[5][P], V, wC.y); \
                    fma2(acc[6][P], V, wD.x); fma2(acc[7][P], V, wD.y);
                STEP8(0, vv0)
                STEP8(1, vv1)
                #undef STEP8
            }
        }
    }

    int gx  = bx0 + tx;
    int dst = src ^ 1;
    const float* c_src_p = g_c[src] + (size_t)b*HC*HW;
    float*       c_dst_p = g_c[dst] + (size_t)b*HC*HW;
    float*       h_dst_p = g_h[dst] + (size_t)b*HC*HW;
    #pragma unroll
    for (int p=0;p<2;p++){
        int gy = by0 + ty*2 + p;
        int pi = gy*Ww + gx;
        float g16[16];
        #pragma unroll
        for (int j=0;j<8;j++) unpack2(acc[j][p], g16[2*j], g16[2*j+1]);
        #pragma unroll
        for (int l=0;l<4;l++){
            int hc = hcg*4 + l;
            float ig = sigmf_fast(g16[l]    + bs[l]);
            float og = sigmf_fast(g16[8+l]  + bs[8+l]);
            float gg = tanhf_fast(g16[12+l] + bs[12+l]);
            float cn;
            if (FIRST){
                cn = ig*gg;                       // f*c0 = 0 exactly
            } else {
                float fg = sigmf_fast(g16[4+l]  + bs[4+l]);
                float cp = c_src_p[(size_t)hc*HW + pi];
                cn = fg*cp + ig*gg;
            }
            c_dst_p[(size_t)hc*HW + pi] = cn;
            h_dst_p[(size_t)hc*HW + pi] = og * tanhf_fast(cn);
        }
    }
}

// ---------------- fused epilogue: mean/wp/gate/head/sigmoid --------------
__global__ void fuse_kernel(const float* __restrict__ sat, const int* __restrict__ months,
                            const float* __restrict__ wp_w, const float* __restrict__ wp_b,
                            const float* __restrict__ head_w, const float* __restrict__ head_b,
                            const float* __restrict__ sg_w1, const float* __restrict__ sg_b1,
                            const float* __restrict__ sg_w2, const float* __restrict__ sg_b2,
                            float* __restrict__ out){
    int idx = blockIdx.x*blockDim.x + threadIdx.x;
    if (idx >= Bsz*HW) return;
    int b = idx / HW, p = idx % HW;

    float s = sat[b];
    float pre = sg_b2[0];
    #pragma unroll
    for (int j=0;j<8;j++){
        float hid = fmaxf(fmaf(sg_w1[j], s, sg_b1[j]), 0.f);
        pre = fmaf(sg_w2[j], hid, pre);
    }
    int m = months[b];
    float prior = (m>=3 && m<=6) ? 0.6f : 0.3f;
    float alpha = prior * sigmf_fast(pre);

    float feat[8];
    #pragma unroll
    for (int c=0;c<8;c++){
        float a = 0.f;
        #pragma unroll
        for (int t=0;t<Tt;t++) a += g_enc[(size_t)((b*Tt+t)*EC+c)*HW + p];
        feat[c] = a * (1.0f/12.0f);
    }

    float res = head_b[0];
    #pragma unroll
    for (int hc=0; hc<16; hc++){
        float haux = wp_b[hc];
        #pragma unroll
        for (int c=0;c<8;c++) haux = fmaf(wp_w[hc*8+c], feat[c], haux);
        float hm = g_h[0][(size_t)(b*HC+hc)*HW + p];   // after 12 steps h lives in buf 0
        res = fmaf(head_w[hc], hm + alpha*haux, res);
    }
    out[idx] = sigmf_fast(res);
}

extern "C" void kernel_launch(void* const* d_in, const int* in_sizes, int n_in,
                              void* d_out, int out_size){
    const float* x       = (const float*)d_in[0];
    const float* sat     = (const float*)d_in[1];
    const int*   months  = (const int*)  d_in[2];
    const float* enc_w1  = (const float*)d_in[3];
    const float* enc_b1  = (const float*)d_in[4];
    const float* enc_w2  = (const float*)d_in[5];
    const float* enc_b2  = (const float*)d_in[6];
    const float* cell_w  = (const float*)d_in[7];
    const float* cell_b  = (const float*)d_in[8];
    const float* wp_w    = (const float*)d_in[9];
    const float* wp_b    = (const float*)d_in[10];
    const float* head_w  = (const float*)d_in[11];
    const float* head_b  = (const float*)d_in[12];
    const float* sg_w1   = (const float*)d_in[13];
    const float* sg_b1   = (const float*)d_in[14];
    const float* sg_w2   = (const float*)d_in[15];
    const float* sg_b2   = (const float*)d_in[16];
    float* out = (float*)d_out;

    dim3 blk256(32, 8);
    permute_w_kernel<<<(4*3456 + 255)/256, 256>>>(cell_w);
    enc12_kernel<<<dim3(8, 16, Bsz*Tt), blk256>>>(x, enc_w1, enc_b1, enc_w2, enc_b2);
    // grid: x = hcg (twins adjacent), y = tile (8x16), z = batch
    dim3 lstm_grid(4, 128, Bsz);
    lstm_step_kernel<true><<<lstm_grid, blk256>>>(cell_b, 0, 0);
    for (int t=1; t<Tt; t++){
        lstm_step_kernel<false><<<lstm_grid, blk256>>>(cell_b, t, t & 1);
    }
    fuse_kernel<<<(Bsz*HW + 255)/256, 256>>>(sat, months, wp_w, wp_b,
                                             head_w, head_b, sg_w1, sg_b1,
                                             sg_w2, sg_b2, out);
}